// round 7
// baseline (speedup 1.0000x reference)
#include <cuda_runtime.h>

#define NN 100000
#define EE 1600000
#define BLK 256
#define EBLK 128   // block size for edge sweeps (MLP=8 per thread)

// ---- device scratch (no allocations allowed) ----
__device__ int    g_src32[EE];
__device__ int    g_dst32[EE];
__device__ float  g_deg[NN];
__device__ float  g_dinv[NN];
__device__ float  g_px[NN];
__device__ float  g_s[NN];
__device__ float2 g_pq[NN];
__device__ float2 g_PQ[NN];
__device__ float  g_agg[NN * 16];
__device__ float  g_c[64];
__device__ int    g_b1zero;
__device__ int    g_is64;

__device__ __forceinline__ int4 ldcs4(const int* p) {
    return __ldcs(reinterpret_cast<const int4*>(p));
}

__device__ __forceinline__ void red2(float2* addr, float2 v) {
    asm volatile("red.add.v2.f32 [%0], {%1, %2};"
                 :: "l"(addr), "f"(v.x), "f"(v.y) : "memory");
}

// ---- setup: dtype probe + fused coefficients + zero degree array ----
__global__ void k_setup(const void* __restrict__ ei, const float* __restrict__ W1,
                        const float* __restrict__ b1, const float* __restrict__ W2,
                        int E, int N) {
    int tid = threadIdx.x;
    if (blockIdx.x == 0) {
        __shared__ int bad;
        if (tid == 0) bad = 0;
        __syncthreads();
        if (tid < E) {
            long long v = ((const long long*)ei)[tid];
            if (v < 0 || v >= (long long)N) atomicExch(&bad, 1);
        }
        __syncthreads();
        if (tid == 0) {
            g_is64 = !bad;
            int z = 1;
            for (int k = 0; k < 16; k++)
                if (b1[k] != 0.f) z = 0;
            g_b1zero = z;
        }
        if (tid < 32) {
            float c1 = 0.f, c2 = 0.f;
#pragma unroll
            for (int k = 0; k < 16; k++) {
                float w  = W1[k];
                float wv = W2[k * 32 + tid];
                c1 += fmaxf(w, 0.f) * wv;
                c2 += fminf(w, 0.f) * wv;
            }
            g_c[tid] = c1;
            g_c[32 + tid] = c2;
        }
    }
    int v = blockIdx.x * BLK + tid;
    if (v < N) {
        g_deg[v] = 0.f;
        bool bz = true;
#pragma unroll
        for (int k = 0; k < 16; k++)
            if (b1[k] != 0.f) bz = false;
        if (!bz) {
            float4 z = make_float4(0.f, 0.f, 0.f, 0.f);
            float4* a = reinterpret_cast<float4*>(&g_agg[v * 16]);
            a[0] = z; a[1] = z; a[2] = z; a[3] = z;
        }
    }
}

// ---- pass 1: degree atomics (+ int64->int32 conversion), 8 edges/thread ----
__global__ void __launch_bounds__(EBLK, 12)
k_deg(const void* __restrict__ eiv, int E) {
    int e0 = 8 * (blockIdx.x * blockDim.x + threadIdx.x);
    if (e0 >= E) return;
    if (g_is64) {
        const long long* ei = (const long long*)eiv;
        if (e0 + 7 < E) {
            longlong2 s01 = __ldcs(reinterpret_cast<const longlong2*>(ei + e0));
            longlong2 s23 = __ldcs(reinterpret_cast<const longlong2*>(ei + e0 + 2));
            longlong2 s45 = __ldcs(reinterpret_cast<const longlong2*>(ei + e0 + 4));
            longlong2 s67 = __ldcs(reinterpret_cast<const longlong2*>(ei + e0 + 6));
            longlong2 d01 = __ldcs(reinterpret_cast<const longlong2*>(ei + E + e0));
            longlong2 d23 = __ldcs(reinterpret_cast<const longlong2*>(ei + E + e0 + 2));
            longlong2 d45 = __ldcs(reinterpret_cast<const longlong2*>(ei + E + e0 + 4));
            longlong2 d67 = __ldcs(reinterpret_cast<const longlong2*>(ei + E + e0 + 6));
            int4 sv0 = make_int4((int)s01.x, (int)s01.y, (int)s23.x, (int)s23.y);
            int4 sv1 = make_int4((int)s45.x, (int)s45.y, (int)s67.x, (int)s67.y);
            int4 dv0 = make_int4((int)d01.x, (int)d01.y, (int)d23.x, (int)d23.y);
            int4 dv1 = make_int4((int)d45.x, (int)d45.y, (int)d67.x, (int)d67.y);
            *reinterpret_cast<int4*>(&g_src32[e0])     = sv0;
            *reinterpret_cast<int4*>(&g_src32[e0 + 4]) = sv1;
            *reinterpret_cast<int4*>(&g_dst32[e0])     = dv0;
            *reinterpret_cast<int4*>(&g_dst32[e0 + 4]) = dv1;
            atomicAdd(&g_deg[dv0.x], 1.f); atomicAdd(&g_deg[dv0.y], 1.f);
            atomicAdd(&g_deg[dv0.z], 1.f); atomicAdd(&g_deg[dv0.w], 1.f);
            atomicAdd(&g_deg[dv1.x], 1.f); atomicAdd(&g_deg[dv1.y], 1.f);
            atomicAdd(&g_deg[dv1.z], 1.f); atomicAdd(&g_deg[dv1.w], 1.f);
        } else {
            for (int e = e0; e < E; e++) {
                int s = (int)ei[e], d = (int)ei[E + e];
                g_src32[e] = s; g_dst32[e] = d;
                atomicAdd(&g_deg[d], 1.f);
            }
        }
    } else {
        const int* dst = (const int*)eiv + E;
        if (e0 + 7 < E) {
            int4 dv0 = ldcs4(dst + e0);
            int4 dv1 = ldcs4(dst + e0 + 4);
            atomicAdd(&g_deg[dv0.x], 1.f); atomicAdd(&g_deg[dv0.y], 1.f);
            atomicAdd(&g_deg[dv0.z], 1.f); atomicAdd(&g_deg[dv0.w], 1.f);
            atomicAdd(&g_deg[dv1.x], 1.f); atomicAdd(&g_deg[dv1.y], 1.f);
            atomicAdd(&g_deg[dv1.z], 1.f); atomicAdd(&g_deg[dv1.w], 1.f);
        } else {
            for (int e = e0; e < E; e++) atomicAdd(&g_deg[dst[e]], 1.f);
        }
    }
}

// ---- pass 2: dinv; px; raw s init ----
__global__ void k_node1(const float* __restrict__ x, int n) {
    int v = blockIdx.x * blockDim.x + threadIdx.x;
    if (v >= n) return;
    float dv  = rsqrtf(g_deg[v] + 1.0f);
    g_dinv[v] = dv;
    float pxv = dv * x[v];
    g_px[v]   = pxv;
    g_s[v]    = pxv;
}

// ---- pass 3: layer-1 raw scatter, 8 edges/thread (MLP=8) ----
__global__ void __launch_bounds__(EBLK, 12)
k_scat1(const void* __restrict__ eiv, int E) {
    const int* srcp = g_is64 ? g_src32 : (const int*)eiv;
    const int* dstp = g_is64 ? g_dst32 : (const int*)eiv + E;
    int e0 = 8 * (blockIdx.x * blockDim.x + threadIdx.x);
    if (e0 >= E) return;
    if (e0 + 7 < E) {
        int4 s0 = ldcs4(srcp + e0);
        int4 s1 = ldcs4(srcp + e0 + 4);
        int4 d0 = ldcs4(dstp + e0);
        int4 d1 = ldcs4(dstp + e0 + 4);
        float a0 = __ldg(&g_px[s0.x]), a1 = __ldg(&g_px[s0.y]);
        float a2 = __ldg(&g_px[s0.z]), a3 = __ldg(&g_px[s0.w]);
        float a4 = __ldg(&g_px[s1.x]), a5 = __ldg(&g_px[s1.y]);
        float a6 = __ldg(&g_px[s1.z]), a7 = __ldg(&g_px[s1.w]);
        atomicAdd(&g_s[d0.x], a0); atomicAdd(&g_s[d0.y], a1);
        atomicAdd(&g_s[d0.z], a2); atomicAdd(&g_s[d0.w], a3);
        atomicAdd(&g_s[d1.x], a4); atomicAdd(&g_s[d1.y], a5);
        atomicAdd(&g_s[d1.z], a6); atomicAdd(&g_s[d1.w], a7);
    } else {
        for (int e = e0; e < E; e++)
            atomicAdd(&g_s[dstp[e]], __ldg(&g_px[srcp[e]]));
    }
}

// ---- pass 4: finalize s; pq split; raw PQ init ----
__global__ void k_node2(int n) {
    int v = blockIdx.x * blockDim.x + threadIdx.x;
    if (v >= n) return;
    float dv = g_dinv[v];
    float s  = dv * g_s[v];
    g_s[v]   = s;
    float p = fmaxf(s, 0.f), q = fminf(s, 0.f);
    float2 pq = make_float2(dv * p, dv * q);
    g_pq[v] = pq;
    g_PQ[v] = pq;
}

// ---- pass 5: layer-2 raw scatter, 8 edges/thread, 1 v2-RED/edge ----
__global__ void __launch_bounds__(EBLK, 12)
k_scat2(const void* __restrict__ eiv,
        const float* __restrict__ W1,
        const float* __restrict__ b1, int E) {
    const int* srcp = g_is64 ? g_src32 : (const int*)eiv;
    const int* dstp = g_is64 ? g_dst32 : (const int*)eiv + E;
    int bz = g_b1zero;
    int e0 = 8 * (blockIdx.x * blockDim.x + threadIdx.x);
    if (e0 >= E) return;
    if (bz) {
        if (e0 + 7 < E) {
            int4 s0 = ldcs4(srcp + e0);
            int4 s1 = ldcs4(srcp + e0 + 4);
            int4 d0 = ldcs4(dstp + e0);
            int4 d1 = ldcs4(dstp + e0 + 4);
            float2 t0 = __ldg(&g_pq[s0.x]), t1 = __ldg(&g_pq[s0.y]);
            float2 t2 = __ldg(&g_pq[s0.z]), t3 = __ldg(&g_pq[s0.w]);
            float2 t4 = __ldg(&g_pq[s1.x]), t5 = __ldg(&g_pq[s1.y]);
            float2 t6 = __ldg(&g_pq[s1.z]), t7 = __ldg(&g_pq[s1.w]);
            red2(&g_PQ[d0.x], t0); red2(&g_PQ[d0.y], t1);
            red2(&g_PQ[d0.z], t2); red2(&g_PQ[d0.w], t3);
            red2(&g_PQ[d1.x], t4); red2(&g_PQ[d1.y], t5);
            red2(&g_PQ[d1.z], t6); red2(&g_PQ[d1.w], t7);
        } else {
            for (int e = e0; e < E; e++) red2(&g_PQ[dstp[e]], __ldg(&g_pq[srcp[e]]));
        }
    } else {
        __shared__ float sW1[16], sb1[16];
        if (threadIdx.x < 16) { sW1[threadIdx.x] = W1[threadIdx.x]; sb1[threadIdx.x] = b1[threadIdx.x]; }
        __syncthreads();
        int eEnd = min(e0 + 8, E);
        for (int e = e0; e < eEnd; e++) {
            int s = srcp[e], d = dstp[e];
            float sv = __ldg(&g_s[s]);
            float ns = __ldg(&g_dinv[s]);
#pragma unroll
            for (int k = 0; k < 16; k++) {
                float h = fmaxf(sv * sW1[k] + sb1[k], 0.f);
                atomicAdd(&g_agg[d * 16 + k], ns * h);
            }
        }
    }
}

// ---- pass 6: output projection (streaming stores) ----
__global__ void k_out(const float* __restrict__ W1, const float* __restrict__ b1,
                      const float* __restrict__ W2, const float* __restrict__ b2,
                      float* __restrict__ out, int n) {
    __shared__ float sc[64];
    __shared__ float sb2[32];
    __shared__ float sW2[512];
    __shared__ float sW1[16], sb1[16];
    int bz = g_b1zero;
    int t = threadIdx.x;
    if (t < 64) sc[t] = g_c[t];
    if (t < 32) sb2[t] = b2[t];
    if (!bz) {
        for (int k = t; k < 512; k += blockDim.x) sW2[k] = W2[k];
        if (t < 16) { sW1[t] = W1[t]; sb1[t] = b1[t]; }
    }
    __syncthreads();
    int v = blockIdx.x * blockDim.x + t;
    if (v >= n) return;

    float o[32];
    float dv = g_dinv[v];
    if (bz) {
        float2 PQ = g_PQ[v];
        float P = dv * PQ.x, Q = dv * PQ.y;
#pragma unroll
        for (int j = 0; j < 32; j++) o[j] = P * sc[j] + Q * sc[32 + j] + sb2[j];
    } else {
        float sv = g_s[v];
        float n2 = dv * dv;
        float tot[16];
#pragma unroll
        for (int k = 0; k < 16; k++) {
            float h = fmaxf(sv * sW1[k] + sb1[k], 0.f);
            tot[k] = dv * g_agg[v * 16 + k] + n2 * h;
        }
#pragma unroll
        for (int j = 0; j < 32; j++) {
            float acc = sb2[j];
#pragma unroll
            for (int k = 0; k < 16; k++) acc += tot[k] * sW2[k * 32 + j];
            o[j] = acc;
        }
    }
    float4* po = reinterpret_cast<float4*>(out + (size_t)v * 32);
#pragma unroll
    for (int j = 0; j < 8; j++)
        __stcs(po + j, make_float4(o[4 * j], o[4 * j + 1], o[4 * j + 2], o[4 * j + 3]));
}

extern "C" void kernel_launch(void* const* d_in, const int* in_sizes, int n_in,
                              void* d_out, int out_size) {
    const float* x  = (const float*)d_in[0];
    const void*  ei = d_in[1];
    const float* W1 = (const float*)d_in[2];
    const float* b1 = (const float*)d_in[3];
    const float* W2 = (const float*)d_in[4];
    const float* b2 = (const float*)d_in[5];
    float* out = (float*)d_out;

    int N = in_sizes[0];
    int E = in_sizes[1] / 2;

    int gN  = (N + BLK - 1) / BLK;
    int gE8 = ((E + 7) / 8 + EBLK - 1) / EBLK;

    k_setup<<<gN, BLK>>>(ei, W1, b1, W2, E, N);
    k_deg<<<gE8, EBLK>>>(ei, E);
    k_node1<<<gN, BLK>>>(x, N);
    k_scat1<<<gE8, EBLK>>>(ei, E);
    k_node2<<<gN, BLK>>>(N);
    k_scat2<<<gE8, EBLK>>>(ei, W1, b1, E);
    k_out<<<gN, BLK>>>(W1, b1, W2, b2, out, N);
}